// round 1
// baseline (speedup 1.0000x reference)
#include <cuda_runtime.h>
#include <math.h>

#define N_USER  50000
#define N_ITEM  100000
#define N_TOTAL 150000
#define NNZ     3000000
#define EMB     64
#define BATCH   4096

// ---------------- scratch (no allocation allowed -> device globals) --------
__device__ float g_ego[(size_t)N_TOTAL * EMB];    // 38.4 MB
__device__ float g_side[(size_t)N_TOTAL * EMB];   // 38.4 MB
__device__ float g_total[(size_t)N_USER * EMB];   // 12.8 MB

// ---------------- init: ego = concat(user_emb, item_emb); total = user part
__global__ void init_kernel(const float* __restrict__ ue,
                            const float* __restrict__ ie) {
    const int U4 = N_USER * EMB / 4;    // 800000
    const int T4 = N_TOTAL * EMB / 4;   // 2400000
    int idx = blockIdx.x * blockDim.x + threadIdx.x;
    if (idx < T4) {
        float4 v;
        if (idx < U4) {
            v = reinterpret_cast<const float4*>(ue)[idx];
            reinterpret_cast<float4*>(g_total)[idx] = v;
        } else {
            v = reinterpret_cast<const float4*>(ie)[idx - U4];
        }
        reinterpret_cast<float4*>(g_ego)[idx] = v;
    }
}

// ---------------- zero side buffer ----------------------------------------
__global__ void zero_side_kernel() {
    const int T4 = N_TOTAL * EMB / 4;
    int idx = blockIdx.x * blockDim.x + threadIdx.x;
    if (idx < T4)
        reinterpret_cast<float4*>(g_side)[idx] = make_float4(0.f, 0.f, 0.f, 0.f);
}

// ---------------- SpMM: side[r] += v * ego[c]  (16 lanes per edge) --------
__global__ void spmm_kernel(const int* __restrict__ rows,
                            const int* __restrict__ cols,
                            const float* __restrict__ vals) {
    int gid  = blockIdx.x * blockDim.x + threadIdx.x;
    int grp  = gid >> 4;           // edge group (16 lanes each)
    int lane = gid & 15;
    int ngrp = (gridDim.x * blockDim.x) >> 4;
    for (int e = grp; e < NNZ; e += ngrp) {
        int   r = __ldg(rows + e);
        int   c = __ldg(cols + e);
        float v = __ldg(vals + e);
        float4 x = *reinterpret_cast<const float4*>(g_ego + (size_t)c * EMB + lane * 4);
        float* dst = g_side + (size_t)r * EMB + lane * 4;
        asm volatile("red.global.add.v4.f32 [%0], {%1, %2, %3, %4};"
                     :: "l"(dst), "f"(x.x * v), "f"(x.y * v),
                        "f"(x.z * v), "f"(x.w * v)
                     : "memory");
    }
}

// ---------------- fused dense layer: ego = lrelu(side @ W + b);
//                  total[:N_USER] += ego / max(||ego||, eps) ----------------
__global__ void __launch_bounds__(128)
layer_kernel(const float* __restrict__ W, const float* __restrict__ b) {
    __shared__ float tile[128 * 65];   // padded: stride-65 -> conflict-free row reads
    __shared__ float sInv[128];
    int tid  = threadIdx.x;
    int row0 = blockIdx.x * 128;

    // stage side tile (coalesced)
    for (int idx = tid; idx < 128 * 64; idx += 128) {
        int r = idx >> 6, c = idx & 63;
        int grow = row0 + r;
        tile[r * 65 + c] = (grow < N_TOTAL) ? g_side[(size_t)grow * 64 + c] : 0.f;
    }
    __syncthreads();

    int row = row0 + tid;
    const float4* W4 = reinterpret_cast<const float4*>(W);
    const float4* b4 = reinterpret_cast<const float4*>(b);
    if (row < N_TOTAL) {
        float acc[64];
#pragma unroll
        for (int j = 0; j < 16; j++) {
            float4 bb = __ldg(b4 + j);
            acc[4 * j]     = bb.x;
            acc[4 * j + 1] = bb.y;
            acc[4 * j + 2] = bb.z;
            acc[4 * j + 3] = bb.w;
        }
        for (int k = 0; k < 64; k++) {
            float s = tile[tid * 65 + k];
#pragma unroll
            for (int j = 0; j < 16; j++) {
                float4 w = __ldg(W4 + k * 16 + j);   // uniform -> L1 broadcast
                acc[4 * j]     += s * w.x;
                acc[4 * j + 1] += s * w.y;
                acc[4 * j + 2] += s * w.z;
                acc[4 * j + 3] += s * w.w;
            }
        }
        float nrm = 0.f;
#pragma unroll
        for (int j = 0; j < 64; j++) {
            float x = acc[j];
            x = (x >= 0.f) ? x : 0.2f * x;   // leaky_relu(0.2)
            acc[j] = x;
            nrm += x * x;
        }
        float norm = sqrtf(nrm);
        sInv[tid] = 1.0f / fmaxf(norm, 1e-12f);
#pragma unroll
        for (int j = 0; j < 64; j++)       // own row only: no hazard pre-sync
            tile[tid * 65 + j] = acc[j];
    }
    __syncthreads();

    // coalesced writeback of ego and total
    for (int idx = tid; idx < 128 * 64; idx += 128) {
        int r = idx >> 6, c = idx & 63;
        int grow = row0 + r;
        if (grow < N_TOTAL) {
            float h = tile[r * 65 + c];
            g_ego[(size_t)grow * 64 + c] = h;
            if (grow < N_USER)
                g_total[(size_t)grow * 64 + c] += h * sInv[r];
        }
    }
}

// ---------------- final gather: out = total[users] -------------------------
__global__ void gather_kernel(const int* __restrict__ users,
                              float* __restrict__ out) {
    int idx = blockIdx.x * blockDim.x + threadIdx.x;  // float4 element of out
    if (idx < BATCH * 16) {
        int i = idx >> 4, j = idx & 15;
        int u = __ldg(users + i);
        reinterpret_cast<float4*>(out)[(size_t)i * 16 + j] =
            reinterpret_cast<const float4*>(g_total)[(size_t)u * 16 + j];
    }
}

// ---------------------------------------------------------------------------
extern "C" void kernel_launch(void* const* d_in, const int* in_sizes, int n_in,
                              void* d_out, int out_size) {
    const int*   users    = (const int*)  d_in[0];
    const int*   rows     = (const int*)  d_in[1];
    const int*   cols     = (const int*)  d_in[2];
    const float* vals     = (const float*)d_in[3];
    const float* user_emb = (const float*)d_in[4];
    const float* item_emb = (const float*)d_in[5];
    const float* Ws[3] = {(const float*)d_in[6], (const float*)d_in[8],  (const float*)d_in[10]};
    const float* bs[3] = {(const float*)d_in[7], (const float*)d_in[9],  (const float*)d_in[11]};
    float* out = (float*)d_out;

    const int T4 = N_TOTAL * EMB / 4;                 // 2.4M float4
    init_kernel<<<(T4 + 255) / 256, 256>>>(user_emb, item_emb);

    for (int l = 0; l < 3; l++) {
        zero_side_kernel<<<(T4 + 255) / 256, 256>>>();
        spmm_kernel<<<8192, 256>>>(rows, cols, vals);
        layer_kernel<<<(N_TOTAL + 127) / 128, 128>>>(Ws[l], bs[l]);
    }

    gather_kernel<<<(BATCH * 16 + 255) / 256, 256>>>(users, out);
}

// round 2
// speedup vs baseline: 1.4282x; 1.4282x over previous
#include <cuda_runtime.h>
#include <math.h>

#define N_USER  50000
#define N_ITEM  100000
#define N_TOTAL 150000
#define NNZ     3000000
#define EMB     64
#define BATCH   4096

// ---------------- scratch (no allocation allowed -> device globals) --------
__device__ float g_ego[(size_t)N_TOTAL * EMB];    // 38.4 MB
__device__ float g_side[(size_t)N_TOTAL * EMB];   // 38.4 MB
__device__ float g_total[(size_t)N_USER * EMB];   // 12.8 MB
__device__ int   g_cnt[N_TOTAL];
__device__ int   g_row_start[N_TOTAL + 1];
__device__ int   g_row_ptr[N_TOTAL];
__device__ int2  g_edge[NNZ];                     // 24 MB (col, val-bits)

// ---------------- packed f32x2 helpers -------------------------------------
__device__ __forceinline__ unsigned long long ffma2(unsigned long long a,
                                                    unsigned long long b,
                                                    unsigned long long c) {
    unsigned long long d;
    asm("fma.rn.f32x2 %0, %1, %2, %3;" : "=l"(d) : "l"(a), "l"(b), "l"(c));
    return d;
}
__device__ __forceinline__ unsigned long long pack2(float lo, float hi) {
    unsigned long long d;
    asm("mov.b64 %0, {%1, %2};" : "=l"(d) : "f"(lo), "f"(hi));
    return d;
}
__device__ __forceinline__ void unpack2(unsigned long long v, float& lo, float& hi) {
    asm("mov.b64 {%0, %1}, %2;" : "=f"(lo), "=f"(hi) : "l"(v));
}

// ---------------- init: ego = concat; total = user part; zero counts ------
__global__ void init_kernel(const float* __restrict__ ue,
                            const float* __restrict__ ie) {
    const int U4 = N_USER * EMB / 4;
    const int T4 = N_TOTAL * EMB / 4;
    int idx = blockIdx.x * blockDim.x + threadIdx.x;
    if (idx < T4) {
        float4 v;
        if (idx < U4) {
            v = reinterpret_cast<const float4*>(ue)[idx];
            reinterpret_cast<float4*>(g_total)[idx] = v;
        } else {
            v = reinterpret_cast<const float4*>(ie)[idx - U4];
        }
        reinterpret_cast<float4*>(g_ego)[idx] = v;
    }
    if (idx < N_TOTAL) g_cnt[idx] = 0;
}

// ---------------- CSR build: histogram -------------------------------------
__global__ void hist_kernel(const int* __restrict__ rows) {
    int idx = blockIdx.x * blockDim.x + threadIdx.x;
    if (idx < NNZ) atomicAdd(&g_cnt[__ldg(rows + idx)], 1);
}

// ---------------- CSR build: single-block scan ------------------------------
__global__ void __launch_bounds__(1024) scan_kernel() {
    __shared__ int ssum[1024];
    const int CH = (N_TOTAL + 1023) / 1024;   // 147
    int t = threadIdx.x;
    int beg = t * CH;
    int end = min(beg + CH, N_TOTAL);
    int s = 0;
    for (int i = beg; i < end; i++) s += g_cnt[i];
    ssum[t] = s;
    __syncthreads();
    for (int off = 1; off < 1024; off <<= 1) {
        int v = (t >= off) ? ssum[t - off] : 0;
        __syncthreads();
        ssum[t] += v;
        __syncthreads();
    }
    int run = (t == 0) ? 0 : ssum[t - 1];
    for (int i = beg; i < end; i++) {
        g_row_start[i] = run;
        g_row_ptr[i]   = run;
        run += g_cnt[i];
    }
    if (t == 1023) g_row_start[N_TOTAL] = NNZ;
}

// ---------------- CSR build: scatter edges ----------------------------------
__global__ void scatter_kernel(const int* __restrict__ rows,
                               const int* __restrict__ cols,
                               const float* __restrict__ vals) {
    int idx = blockIdx.x * blockDim.x + threadIdx.x;
    if (idx < NNZ) {
        int r = __ldg(rows + idx);
        int pos = atomicAdd(&g_row_ptr[r], 1);
        g_edge[pos] = make_int2(__ldg(cols + idx),
                                __float_as_int(__ldg(vals + idx)));
    }
}

// ---------------- pull SpMM: one warp per row, no atomics -------------------
__global__ void __launch_bounds__(256) spmm_pull_kernel() {
    int lane = threadIdx.x & 31;
    int wid  = (blockIdx.x * blockDim.x + threadIdx.x) >> 5;
    if (wid >= N_TOTAL) return;
    int s = __ldg(&g_row_start[wid]);
    int e = __ldg(&g_row_start[wid + 1]);
    float2 acc = make_float2(0.f, 0.f);
    for (int i = s; i < e; i++) {
        int2 ed = __ldg(&g_edge[i]);              // broadcast within warp
        float v = __int_as_float(ed.y);
        float2 x = *reinterpret_cast<const float2*>(
            g_ego + (size_t)ed.x * EMB + lane * 2);
        acc.x += v * x.x;
        acc.y += v * x.y;
    }
    reinterpret_cast<float2*>(g_side + (size_t)wid * EMB)[lane] = acc;
}

// ---------------- fused dense layer (64x64 tile, 4x4 per thread, FFMA2) -----
// ego = lrelu(side @ W + b); total[:N_USER] += ego / max(||ego||, eps)
__global__ void __launch_bounds__(256)
layer_kernel(const float* __restrict__ W, const float* __restrict__ b) {
    __shared__ float sW[64 * 64];     // 16 KB
    __shared__ float sS[64 * 65];     // 16.6 KB, padded rows (reused for output)
    __shared__ float sInv[64];

    int tid = threadIdx.x;
    int tc  = tid & 15;               // col group (16)
    int tr  = tid >> 4;               // row group (16)
    int row0 = blockIdx.x * 64;

    // stage W (coalesced float4)
    for (int i = tid; i < 1024; i += 256)
        reinterpret_cast<float4*>(sW)[i] =
            __ldg(reinterpret_cast<const float4*>(W) + i);
    // stage side tile (coalesced float4 loads, scalar padded stores)
    for (int i = tid; i < 1024; i += 256) {
        int r  = i >> 4;
        int c4 = i & 15;
        int grow = row0 + r;
        float4 v = (grow < N_TOTAL)
            ? __ldg(reinterpret_cast<const float4*>(g_side + (size_t)grow * 64) + c4)
            : make_float4(0.f, 0.f, 0.f, 0.f);
        float* p = sS + r * 65 + c4 * 4;
        p[0] = v.x; p[1] = v.y; p[2] = v.z; p[3] = v.w;
    }
    __syncthreads();

    int r0 = tr * 4, c0 = tc * 4;
    // acc[r][cpair], cpair 0 = cols (c0,c0+1), 1 = (c0+2,c0+3)
    unsigned long long acc[4][2];
    {
        float4 bb = __ldg(reinterpret_cast<const float4*>(b) + tc);
        unsigned long long b01 = pack2(bb.x, bb.y);
        unsigned long long b23 = pack2(bb.z, bb.w);
#pragma unroll
        for (int r = 0; r < 4; r++) { acc[r][0] = b01; acc[r][1] = b23; }
    }

#pragma unroll 4
    for (int k = 0; k < 64; k++) {
        // W row k, 4 cols (one LDS128)
        float4 w = *reinterpret_cast<const float4*>(sW + k * 64 + c0);
        unsigned long long w01 = pack2(w.x, w.y);
        unsigned long long w23 = pack2(w.z, w.w);
#pragma unroll
        for (int r = 0; r < 4; r++) {
            float s = sS[(r0 + r) * 65 + k];       // broadcast (2 addrs/warp)
            unsigned long long sd = pack2(s, s);
            acc[r][0] = ffma2(sd, w01, acc[r][0]);
            acc[r][1] = ffma2(sd, w23, acc[r][1]);
        }
    }

    // epilogue: lrelu + per-row sum of squares (partial over this thread's 4 cols)
    float h[4][4];
    float sq[4];
#pragma unroll
    for (int r = 0; r < 4; r++) {
        float x0, x1, x2, x3;
        unpack2(acc[r][0], x0, x1);
        unpack2(acc[r][1], x2, x3);
        x0 = (x0 >= 0.f) ? x0 : 0.2f * x0;
        x1 = (x1 >= 0.f) ? x1 : 0.2f * x1;
        x2 = (x2 >= 0.f) ? x2 : 0.2f * x2;
        x3 = (x3 >= 0.f) ? x3 : 0.2f * x3;
        h[r][0] = x0; h[r][1] = x1; h[r][2] = x2; h[r][3] = x3;
        sq[r] = x0 * x0 + x1 * x1 + x2 * x2 + x3 * x3;
    }
    // reduce over the 16 col-threads (width-16 shuffle groups)
#pragma unroll
    for (int off = 8; off > 0; off >>= 1) {
#pragma unroll
        for (int r = 0; r < 4; r++)
            sq[r] += __shfl_down_sync(0xffffffffu, sq[r], off, 16);
    }

    __syncthreads();   // everyone done reading sS -> safe to overwrite
    if (tc == 0) {
#pragma unroll
        for (int r = 0; r < 4; r++)
            sInv[r0 + r] = 1.0f / fmaxf(sqrtf(sq[r]), 1e-12f);
    }
#pragma unroll
    for (int r = 0; r < 4; r++) {
        float* p = sS + (r0 + r) * 65 + c0;
        p[0] = h[r][0]; p[1] = h[r][1]; p[2] = h[r][2]; p[3] = h[r][3];
    }
    __syncthreads();

    // coalesced writeback of ego and total
    for (int i = tid; i < 4096; i += 256) {
        int r = i >> 6, c = i & 63;
        int grow = row0 + r;
        if (grow < N_TOTAL) {
            float v = sS[r * 65 + c];
            g_ego[(size_t)grow * 64 + c] = v;
            if (grow < N_USER)
                g_total[(size_t)grow * 64 + c] += v * sInv[r];
        }
    }
}

// ---------------- final gather: out = total[users] -------------------------
__global__ void gather_kernel(const int* __restrict__ users,
                              float* __restrict__ out) {
    int idx = blockIdx.x * blockDim.x + threadIdx.x;
    if (idx < BATCH * 16) {
        int i = idx >> 4, j = idx & 15;
        int u = __ldg(users + i);
        reinterpret_cast<float4*>(out)[(size_t)i * 16 + j] =
            reinterpret_cast<const float4*>(g_total)[(size_t)u * 16 + j];
    }
}

// ---------------------------------------------------------------------------
extern "C" void kernel_launch(void* const* d_in, const int* in_sizes, int n_in,
                              void* d_out, int out_size) {
    const int*   users    = (const int*)  d_in[0];
    const int*   rows     = (const int*)  d_in[1];
    const int*   cols     = (const int*)  d_in[2];
    const float* vals     = (const float*)d_in[3];
    const float* user_emb = (const float*)d_in[4];
    const float* item_emb = (const float*)d_in[5];
    const float* Ws[3] = {(const float*)d_in[6], (const float*)d_in[8],  (const float*)d_in[10]};
    const float* bs[3] = {(const float*)d_in[7], (const float*)d_in[9],  (const float*)d_in[11]};
    float* out = (float*)d_out;

    const int T4 = N_TOTAL * EMB / 4;
    init_kernel<<<(T4 + 255) / 256, 256>>>(user_emb, item_emb);
    hist_kernel<<<(NNZ + 255) / 256, 256>>>(rows);
    scan_kernel<<<1, 1024>>>();
    scatter_kernel<<<(NNZ + 255) / 256, 256>>>(rows, cols, vals);

    const int spmm_blocks = (N_TOTAL * 32 + 255) / 256;   // one warp per row
    const int layer_blocks = (N_TOTAL + 63) / 64;
    for (int l = 0; l < 3; l++) {
        spmm_pull_kernel<<<spmm_blocks, 256>>>();
        layer_kernel<<<layer_blocks, 256>>>(Ws[l], bs[l]);
    }

    gather_kernel<<<(BATCH * 16 + 255) / 256, 256>>>(users, out);
}

// round 3
// speedup vs baseline: 2.2493x; 1.5749x over previous
#include <cuda_runtime.h>
#include <math.h>

#define N_USER  50000
#define N_ITEM  100000
#define N_TOTAL 150000
#define NNZ     3000000
#define EMB     64
#define BATCH   4096
#define SCAN_BLKS 147   // ceil(150000/1024)

// ---------------- scratch (no allocation allowed -> device globals) --------
__device__ float g_bufA[(size_t)N_TOTAL * EMB];   // 38.4 MB (ego ping)
__device__ float g_bufB[(size_t)N_TOTAL * EMB];   // 38.4 MB (ego pong)
__device__ float g_total[(size_t)N_USER * EMB];   // 12.8 MB
__device__ int   g_cnt[N_TOTAL];
__device__ int   g_row_start[N_TOTAL + 1];
__device__ int   g_row_ptr[N_TOTAL];
__device__ int   g_blk[256];
__device__ int2  g_edge[NNZ];                     // 24 MB (col, val-bits)

// ---------------- packed f32x2 helpers -------------------------------------
__device__ __forceinline__ unsigned long long ffma2(unsigned long long a,
                                                    unsigned long long b,
                                                    unsigned long long c) {
    unsigned long long d;
    asm("fma.rn.f32x2 %0, %1, %2, %3;" : "=l"(d) : "l"(a), "l"(b), "l"(c));
    return d;
}
__device__ __forceinline__ unsigned long long pack2(float lo, float hi) {
    unsigned long long d;
    asm("mov.b64 %0, {%1, %2};" : "=l"(d) : "f"(lo), "f"(hi));
    return d;
}
__device__ __forceinline__ void unpack2(unsigned long long v, float& lo, float& hi) {
    asm("mov.b64 {%0, %1}, %2;" : "=f"(lo), "=f"(hi) : "l"(v));
}

// ---------------- init: ego = concat; total = user part; zero counts ------
__global__ void init_kernel(const float* __restrict__ ue,
                            const float* __restrict__ ie) {
    const int U4 = N_USER * EMB / 4;
    const int T4 = N_TOTAL * EMB / 4;
    int idx = blockIdx.x * blockDim.x + threadIdx.x;
    if (idx < T4) {
        float4 v;
        if (idx < U4) {
            v = reinterpret_cast<const float4*>(ue)[idx];
            reinterpret_cast<float4*>(g_total)[idx] = v;
        } else {
            v = reinterpret_cast<const float4*>(ie)[idx - U4];
        }
        reinterpret_cast<float4*>(g_bufA)[idx] = v;
    }
    if (idx < N_TOTAL) g_cnt[idx] = 0;
}

// ---------------- CSR build: histogram -------------------------------------
__global__ void hist_kernel(const int* __restrict__ rows) {
    int idx = blockIdx.x * blockDim.x + threadIdx.x;
    if (idx < NNZ) atomicAdd(&g_cnt[__ldg(rows + idx)], 1);
}

// ---------------- hierarchical scan (A: per-block, B: block sums, C: add) ---
__global__ void __launch_bounds__(1024) scanA_kernel() {
    __shared__ int sh[1024];
    int t = threadIdx.x;
    int i = blockIdx.x * 1024 + t;
    int v = (i < N_TOTAL) ? g_cnt[i] : 0;
    sh[t] = v;
    __syncthreads();
    for (int off = 1; off < 1024; off <<= 1) {
        int x = (t >= off) ? sh[t - off] : 0;
        __syncthreads();
        sh[t] += x;
        __syncthreads();
    }
    if (i < N_TOTAL) g_row_start[i] = sh[t] - v;  // exclusive within block
    if (t == 1023) g_blk[blockIdx.x] = sh[1023];
}
__global__ void __launch_bounds__(256) scanB_kernel() {
    __shared__ int sh[256];
    int t = threadIdx.x;
    int v = (t < SCAN_BLKS) ? g_blk[t] : 0;
    sh[t] = v;
    __syncthreads();
    for (int off = 1; off < 256; off <<= 1) {
        int x = (t >= off) ? sh[t - off] : 0;
        __syncthreads();
        sh[t] += x;
        __syncthreads();
    }
    if (t < SCAN_BLKS) g_blk[t] = sh[t] - v;      // exclusive block offsets
}
__global__ void __launch_bounds__(1024) scanC_kernel() {
    int i = blockIdx.x * 1024 + threadIdx.x;
    if (i < N_TOTAL) {
        int v = g_row_start[i] + g_blk[blockIdx.x];
        g_row_start[i] = v;
        g_row_ptr[i]   = v;
    }
    if (i == 0) g_row_start[N_TOTAL] = NNZ;
}

// ---------------- CSR build: scatter edges ----------------------------------
__global__ void scatter_kernel(const int* __restrict__ rows,
                               const int* __restrict__ cols,
                               const float* __restrict__ vals) {
    int idx = blockIdx.x * blockDim.x + threadIdx.x;
    if (idx < NNZ) {
        int r = __ldg(rows + idx);
        int pos = atomicAdd(&g_row_ptr[r], 1);
        g_edge[pos] = make_int2(__ldg(cols + idx),
                                __float_as_int(__ldg(vals + idx)));
    }
}

// ---------------- fused SpMM + dense layer ----------------------------------
// side = segment_sum (pulled into smem); ego_dst = lrelu(side @ W + b);
// total[:N_USER] += ego / max(||ego||, eps)
template <int WRITE_EGO>
__global__ void __launch_bounds__(256)
fused_layer_kernel(const float* __restrict__ ego_src,
                   float* __restrict__ ego_dst,
                   const float* __restrict__ W, const float* __restrict__ b) {
    __shared__ float sW[64 * 64];     // 16 KB
    __shared__ float sS[64 * 66];     // 16.9 KB padded (stride 66 keeps f2 align)
    __shared__ float sInv[64];

    int tid  = threadIdx.x;
    int row0 = blockIdx.x * 64;
    int warp = tid >> 5, lane = tid & 31;

    // stage W (coalesced float4)
    for (int i = tid; i < 1024; i += 256)
        reinterpret_cast<float4*>(sW)[i] =
            __ldg(reinterpret_cast<const float4*>(W) + i);

    // ---- phase 1: pull-SpMM, one warp per row (8 rows/warp), into sS ------
    for (int rr = warp; rr < 64; rr += 8) {
        int grow = row0 + rr;
        float2 acc = make_float2(0.f, 0.f);
        if (grow < N_TOTAL) {
            int s = __ldg(&g_row_start[grow]);
            int e = __ldg(&g_row_start[grow + 1]);
            for (int i = s; i < e; i++) {
                int2 ed = __ldg(&g_edge[i]);          // warp-uniform broadcast
                float v = __int_as_float(ed.y);
                float2 x = *reinterpret_cast<const float2*>(
                    ego_src + (size_t)ed.x * EMB + lane * 2);
                acc.x += v * x.x;
                acc.y += v * x.y;
            }
        }
        *reinterpret_cast<float2*>(&sS[rr * 66 + lane * 2]) = acc;
    }
    __syncthreads();

    // ---- phase 2: 64x64 GEMM, 4x4 per thread, FFMA2 -----------------------
    int tc = tid & 15, tr = tid >> 4;
    int r0 = tr * 4, c0 = tc * 4;
    unsigned long long acc[4][2];
    {
        float4 bb = __ldg(reinterpret_cast<const float4*>(b) + tc);
        unsigned long long b01 = pack2(bb.x, bb.y);
        unsigned long long b23 = pack2(bb.z, bb.w);
#pragma unroll
        for (int r = 0; r < 4; r++) { acc[r][0] = b01; acc[r][1] = b23; }
    }
#pragma unroll 4
    for (int k = 0; k < 64; k++) {
        float4 w = *reinterpret_cast<const float4*>(sW + k * 64 + c0);
        unsigned long long w01 = pack2(w.x, w.y);
        unsigned long long w23 = pack2(w.z, w.w);
#pragma unroll
        for (int r = 0; r < 4; r++) {
            float s = sS[(r0 + r) * 66 + k];
            unsigned long long sd = pack2(s, s);
            acc[r][0] = ffma2(sd, w01, acc[r][0]);
            acc[r][1] = ffma2(sd, w23, acc[r][1]);
        }
    }

    // epilogue: lrelu + per-row sum of squares
    float h[4][4];
    float sq[4];
#pragma unroll
    for (int r = 0; r < 4; r++) {
        float x0, x1, x2, x3;
        unpack2(acc[r][0], x0, x1);
        unpack2(acc[r][1], x2, x3);
        x0 = (x0 >= 0.f) ? x0 : 0.2f * x0;
        x1 = (x1 >= 0.f) ? x1 : 0.2f * x1;
        x2 = (x2 >= 0.f) ? x2 : 0.2f * x2;
        x3 = (x3 >= 0.f) ? x3 : 0.2f * x3;
        h[r][0] = x0; h[r][1] = x1; h[r][2] = x2; h[r][3] = x3;
        sq[r] = x0 * x0 + x1 * x1 + x2 * x2 + x3 * x3;
    }
#pragma unroll
    for (int off = 8; off > 0; off >>= 1) {
#pragma unroll
        for (int r = 0; r < 4; r++)
            sq[r] += __shfl_down_sync(0xffffffffu, sq[r], off, 16);
    }

    __syncthreads();   // done reading sS -> safe to overwrite
    if (tc == 0) {
#pragma unroll
        for (int r = 0; r < 4; r++)
            sInv[r0 + r] = 1.0f / fmaxf(sqrtf(sq[r]), 1e-12f);
    }
#pragma unroll
    for (int r = 0; r < 4; r++) {
        float* p = sS + (r0 + r) * 66 + c0;
        p[0] = h[r][0]; p[1] = h[r][1]; p[2] = h[r][2]; p[3] = h[r][3];
    }
    __syncthreads();

    // coalesced writeback: ego (layers 0,1) and total (user rows)
    for (int i = tid; i < 4096; i += 256) {
        int r = i >> 6, c = i & 63;
        int grow = row0 + r;
        if (grow < N_TOTAL) {
            float v = sS[r * 66 + c];
            if (WRITE_EGO)
                ego_dst[(size_t)grow * 64 + c] = v;
            if (grow < N_USER)
                g_total[(size_t)grow * 64 + c] += v * sInv[r];
        }
    }
}

// ---------------- final gather: out = total[users] -------------------------
__global__ void gather_kernel(const int* __restrict__ users,
                              float* __restrict__ out) {
    int idx = blockIdx.x * blockDim.x + threadIdx.x;
    if (idx < BATCH * 16) {
        int i = idx >> 4, j = idx & 15;
        int u = __ldg(users + i);
        reinterpret_cast<float4*>(out)[(size_t)i * 16 + j] =
            reinterpret_cast<const float4*>(g_total)[(size_t)u * 16 + j];
    }
}

// ---------------------------------------------------------------------------
extern "C" void kernel_launch(void* const* d_in, const int* in_sizes, int n_in,
                              void* d_out, int out_size) {
    const int*   users    = (const int*)  d_in[0];
    const int*   rows     = (const int*)  d_in[1];
    const int*   cols     = (const int*)  d_in[2];
    const float* vals     = (const float*)d_in[3];
    const float* user_emb = (const float*)d_in[4];
    const float* item_emb = (const float*)d_in[5];
    const float* Ws[3] = {(const float*)d_in[6], (const float*)d_in[8],  (const float*)d_in[10]};
    const float* bs[3] = {(const float*)d_in[7], (const float*)d_in[9],  (const float*)d_in[11]};
    float* out = (float*)d_out;

    float* bufA; cudaGetSymbolAddress((void**)&bufA, g_bufA);
    float* bufB; cudaGetSymbolAddress((void**)&bufB, g_bufB);

    const int T4 = N_TOTAL * EMB / 4;
    init_kernel<<<(T4 + 255) / 256, 256>>>(user_emb, item_emb);
    hist_kernel<<<(NNZ + 255) / 256, 256>>>(rows);
    scanA_kernel<<<SCAN_BLKS, 1024>>>();
    scanB_kernel<<<1, 256>>>();
    scanC_kernel<<<SCAN_BLKS, 1024>>>();
    scatter_kernel<<<(NNZ + 255) / 256, 256>>>(rows, cols, vals);

    const int layer_blocks = (N_TOTAL + 63) / 64;
    fused_layer_kernel<1><<<layer_blocks, 256>>>(bufA, bufB, Ws[0], bs[0]);
    fused_layer_kernel<1><<<layer_blocks, 256>>>(bufB, bufA, Ws[1], bs[1]);
    fused_layer_kernel<0><<<layer_blocks, 256>>>(bufA, bufB, Ws[2], bs[2]);

    gather_kernel<<<(BATCH * 16 + 255) / 256, 256>>>(users, out);
}

// round 5
// speedup vs baseline: 2.6424x; 1.1748x over previous
#include <cuda_runtime.h>
#include <cuda_fp16.h>
#include <math.h>

#define N_USER  50000
#define N_ITEM  100000
#define N_TOTAL 150000
#define NNZ     3000000
#define EMB     64
#define BATCH   4096
#define SCAN_BLKS 147   // ceil(150000/1024)

// ---------------- scratch (no allocation allowed -> device globals) --------
__device__ __half2 g_egoA[(size_t)N_TOTAL * 32];  // 19.2 MB (ego ping, fp16)
__device__ __half2 g_egoB[(size_t)N_TOTAL * 32];  // 19.2 MB (ego pong, fp16)
__device__ float   g_total[(size_t)N_USER * EMB]; // 12.8 MB (only used rows touched)
__device__ unsigned char g_used[N_USER];
__device__ int   g_cnt[N_TOTAL];
__device__ int   g_row_start[N_TOTAL + 1];
__device__ int   g_row_ptr[N_TOTAL];
__device__ int   g_blk[256];
__device__ int2  g_edge[NNZ];                     // 24 MB (col, val-bits)

// ---------------- packed f32x2 helpers -------------------------------------
__device__ __forceinline__ unsigned long long ffma2(unsigned long long a,
                                                    unsigned long long b,
                                                    unsigned long long c) {
    unsigned long long d;
    asm("fma.rn.f32x2 %0, %1, %2, %3;" : "=l"(d) : "l"(a), "l"(b), "l"(c));
    return d;
}
__device__ __forceinline__ unsigned long long pack2(float lo, float hi) {
    unsigned long long d;
    asm("mov.b64 %0, {%1, %2};" : "=l"(d) : "f"(lo), "f"(hi));
    return d;
}
__device__ __forceinline__ void unpack2(unsigned long long v, float& lo, float& hi) {
    asm("mov.b64 {%0, %1}, %2;" : "=f"(lo), "=f"(hi) : "l"(v));
}

// ---------------- init: egoA = fp16(concat); zero cnt/total/used ----------
__global__ void init_kernel(const float* __restrict__ ue,
                            const float* __restrict__ ie) {
    const int U4 = N_USER * EMB / 4;    // 800000
    const int T4 = N_TOTAL * EMB / 4;   // 2400000
    int idx = blockIdx.x * blockDim.x + threadIdx.x;
    if (idx < T4) {
        float4 v = (idx < U4)
            ? reinterpret_cast<const float4*>(ue)[idx]
            : reinterpret_cast<const float4*>(ie)[idx - U4];
        g_egoA[2 * idx]     = __floats2half2_rn(v.x, v.y);
        g_egoA[2 * idx + 1] = __floats2half2_rn(v.z, v.w);
        if (idx < U4)
            reinterpret_cast<float4*>(g_total)[idx] = make_float4(0.f, 0.f, 0.f, 0.f);
    }
    if (idx < N_TOTAL) g_cnt[idx] = 0;
    if (idx < N_USER)  g_used[idx] = 0;
}

// ---------------- mark sampled users ---------------------------------------
__global__ void mark_kernel(const int* __restrict__ users) {
    int i = blockIdx.x * blockDim.x + threadIdx.x;
    if (i < BATCH) g_used[__ldg(users + i)] = 1;
}

// ---------------- CSR build: histogram -------------------------------------
__global__ void hist_kernel(const int* __restrict__ rows) {
    int idx = blockIdx.x * blockDim.x + threadIdx.x;
    if (idx < NNZ) atomicAdd(&g_cnt[__ldg(rows + idx)], 1);
}

// ---------------- hierarchical scan (A: per-block, B: block sums, C: add) ---
__global__ void __launch_bounds__(1024) scanA_kernel() {
    __shared__ int sh[1024];
    int t = threadIdx.x;
    int i = blockIdx.x * 1024 + t;
    int v = (i < N_TOTAL) ? g_cnt[i] : 0;
    sh[t] = v;
    __syncthreads();
    for (int off = 1; off < 1024; off <<= 1) {
        int x = (t >= off) ? sh[t - off] : 0;
        __syncthreads();
        sh[t] += x;
        __syncthreads();
    }
    if (i < N_TOTAL) g_row_start[i] = sh[t] - v;  // exclusive within block
    if (t == 1023) g_blk[blockIdx.x] = sh[1023];
}
__global__ void __launch_bounds__(256) scanB_kernel() {
    __shared__ int sh[256];
    int t = threadIdx.x;
    int v = (t < SCAN_BLKS) ? g_blk[t] : 0;
    sh[t] = v;
    __syncthreads();
    for (int off = 1; off < 256; off <<= 1) {
        int x = (t >= off) ? sh[t - off] : 0;
        __syncthreads();
        sh[t] += x;
        __syncthreads();
    }
    if (t < SCAN_BLKS) g_blk[t] = sh[t] - v;      // exclusive block offsets
}
__global__ void __launch_bounds__(1024) scanC_kernel() {
    int i = blockIdx.x * 1024 + threadIdx.x;
    if (i < N_TOTAL) {
        int v = g_row_start[i] + g_blk[blockIdx.x];
        g_row_start[i] = v;
        g_row_ptr[i]   = v;
    }
    if (i == 0) g_row_start[N_TOTAL] = NNZ;
}

// ---------------- CSR build: scatter edges ----------------------------------
__global__ void scatter_kernel(const int* __restrict__ rows,
                               const int* __restrict__ cols,
                               const float* __restrict__ vals) {
    int idx = blockIdx.x * blockDim.x + threadIdx.x;
    if (idx < NNZ) {
        int r = __ldg(rows + idx);
        int pos = atomicAdd(&g_row_ptr[r], 1);
        g_edge[pos] = make_int2(__ldg(cols + idx),
                                __float_as_int(__ldg(vals + idx)));
    }
}

// ---------------- fused SpMM + dense layer ----------------------------------
// side = segment_sum (pulled into smem, fp16 gather / fp32 accumulate);
// ego_dst = fp16(lrelu(side @ W + b)); total[used users] += ego/max(||ego||,eps)
template <int WRITE_EGO>
__global__ void __launch_bounds__(256)
fused_layer_kernel(const __half2* __restrict__ ego_src,
                   __half2* __restrict__ ego_dst,
                   const float* __restrict__ W, const float* __restrict__ b) {
    __shared__ float sW[64 * 64];     // 16 KB
    __shared__ float sS[64 * 66];     // 16.9 KB padded
    __shared__ float sInv[64];
    __shared__ unsigned char sUse[64];

    int tid  = threadIdx.x;
    int row0 = blockIdx.x * 64;
    int warp = tid >> 5, lane = tid & 31;

    // stage W (coalesced float4)
    for (int i = tid; i < 1024; i += 256)
        reinterpret_cast<float4*>(sW)[i] =
            __ldg(reinterpret_cast<const float4*>(W) + i);
    if (tid < 64) {
        int grow = row0 + tid;
        sUse[tid] = (grow < N_USER) ? g_used[grow] : 0;
    }

    // ---- phase 1: pull-SpMM, one warp per row (8 rows/warp), into sS ------
    for (int rr = warp; rr < 64; rr += 8) {
        int grow = row0 + rr;
        float acc0 = 0.f, acc1 = 0.f;
        if (grow < N_TOTAL) {
            int s = __ldg(&g_row_start[grow]);
            int e = __ldg(&g_row_start[grow + 1]);
            int i = s;
            for (; i + 2 <= e; i += 2) {
                int2 e0 = __ldg(&g_edge[i]);
                int2 e1 = __ldg(&g_edge[i + 1]);
                __half2 x0 = __ldg(ego_src + (size_t)e0.x * 32 + lane);
                __half2 x1 = __ldg(ego_src + (size_t)e1.x * 32 + lane);
                float v0 = __int_as_float(e0.y);
                float v1 = __int_as_float(e1.y);
                float2 f0 = __half22float2(x0);
                float2 f1 = __half22float2(x1);
                acc0 += v0 * f0.x + v1 * f1.x;
                acc1 += v0 * f0.y + v1 * f1.y;
            }
            if (i < e) {
                int2 e0 = __ldg(&g_edge[i]);
                __half2 x0 = __ldg(ego_src + (size_t)e0.x * 32 + lane);
                float v0 = __int_as_float(e0.y);
                float2 f0 = __half22float2(x0);
                acc0 += v0 * f0.x;
                acc1 += v0 * f0.y;
            }
        }
        sS[rr * 66 + lane * 2]     = acc0;
        sS[rr * 66 + lane * 2 + 1] = acc1;
    }
    __syncthreads();

    // ---- phase 2: 64x64 GEMM, 4x4 per thread, FFMA2 -----------------------
    int tc = tid & 15, tr = tid >> 4;
    int r0 = tr * 4, c0 = tc * 4;
    unsigned long long acc[4][2];
    {
        float4 bb = __ldg(reinterpret_cast<const float4*>(b) + tc);
        unsigned long long b01 = pack2(bb.x, bb.y);
        unsigned long long b23 = pack2(bb.z, bb.w);
#pragma unroll
        for (int r = 0; r < 4; r++) { acc[r][0] = b01; acc[r][1] = b23; }
    }
#pragma unroll 4
    for (int k = 0; k < 64; k++) {
        float4 w = *reinterpret_cast<const float4*>(sW + k * 64 + c0);
        unsigned long long w01 = pack2(w.x, w.y);
        unsigned long long w23 = pack2(w.z, w.w);
#pragma unroll
        for (int r = 0; r < 4; r++) {
            float s = sS[(r0 + r) * 66 + k];
            unsigned long long sd = pack2(s, s);
            acc[r][0] = ffma2(sd, w01, acc[r][0]);
            acc[r][1] = ffma2(sd, w23, acc[r][1]);
        }
    }

    // epilogue: lrelu + per-row sum of squares
    float h[4][4];
    float sq[4];
#pragma unroll
    for (int r = 0; r < 4; r++) {
        float x0, x1, x2, x3;
        unpack2(acc[r][0], x0, x1);
        unpack2(acc[r][1], x2, x3);
        x0 = (x0 >= 0.f) ? x0 : 0.2f * x0;
        x1 = (x1 >= 0.f) ? x1 : 0.2f * x1;
        x2 = (x2 >= 0.f) ? x2 : 0.2f * x2;
        x3 = (x3 >= 0.f) ? x3 : 0.2f * x3;
        h[r][0] = x0; h[r][1] = x1; h[r][2] = x2; h[r][3] = x3;
        sq[r] = x0 * x0 + x1 * x1 + x2 * x2 + x3 * x3;
    }
#pragma unroll
    for (int off = 8; off > 0; off >>= 1) {
#pragma unroll
        for (int r = 0; r < 4; r++)
            sq[r] += __shfl_down_sync(0xffffffffu, sq[r], off, 16);
    }

    __syncthreads();   // done reading sS -> safe to overwrite
    if (tc == 0) {
#pragma unroll
        for (int r = 0; r < 4; r++)
            sInv[r0 + r] = 1.0f / fmaxf(sqrtf(sq[r]), 1e-12f);
    }
#pragma unroll
    for (int r = 0; r < 4; r++) {
        float* p = sS + (r0 + r) * 66 + c0;
        p[0] = h[r][0]; p[1] = h[r][1]; p[2] = h[r][2]; p[3] = h[r][3];
    }
    __syncthreads();

    // writeback ego (fp16, coalesced)
    if (WRITE_EGO) {
        for (int i = tid; i < 2048; i += 256) {
            int r = i >> 5, c2 = i & 31;
            int grow = row0 + r;
            if (grow < N_TOTAL) {
                float lo = sS[r * 66 + c2 * 2];
                float hi = sS[r * 66 + c2 * 2 + 1];
                ego_dst[(size_t)grow * 32 + c2] = __floats2half2_rn(lo, hi);
            }
        }
    }
    // writeback total (fp32) only for sampled user rows
    for (int i = tid; i < 4096; i += 256) {
        int r = i >> 6, c = i & 63;
        if (sUse[r]) {
            int grow = row0 + r;
            g_total[(size_t)grow * 64 + c] += sS[r * 66 + c] * sInv[r];
        }
    }
}

// ---------------- final gather: out = user_emb[users] + total[users] -------
__global__ void gather_kernel(const int* __restrict__ users,
                              const float* __restrict__ ue,
                              float* __restrict__ out) {
    int idx = blockIdx.x * blockDim.x + threadIdx.x;
    if (idx < BATCH * 16) {
        int i = idx >> 4, j = idx & 15;
        int u = __ldg(users + i);
        float4 a = reinterpret_cast<const float4*>(ue)[(size_t)u * 16 + j];
        float4 t = reinterpret_cast<const float4*>(g_total)[(size_t)u * 16 + j];
        reinterpret_cast<float4*>(out)[(size_t)i * 16 + j] =
            make_float4(a.x + t.x, a.y + t.y, a.z + t.z, a.w + t.w);
    }
}

// ---------------------------------------------------------------------------
extern "C" void kernel_launch(void* const* d_in, const int* in_sizes, int n_in,
                              void* d_out, int out_size) {
    const int*   users    = (const int*)  d_in[0];
    const int*   rows     = (const int*)  d_in[1];
    const int*   cols     = (const int*)  d_in[2];
    const float* vals     = (const float*)d_in[3];
    const float* user_emb = (const float*)d_in[4];
    const float* item_emb = (const float*)d_in[5];
    const float* Ws[3] = {(const float*)d_in[6], (const float*)d_in[8],  (const float*)d_in[10]};
    const float* bs[3] = {(const float*)d_in[7], (const float*)d_in[9],  (const float*)d_in[11]};
    float* out = (float*)d_out;

    __half2* egoA; cudaGetSymbolAddress((void**)&egoA, g_egoA);
    __half2* egoB; cudaGetSymbolAddress((void**)&egoB, g_egoB);

    const int T4 = N_TOTAL * EMB / 4;
    init_kernel<<<(T4 + 255) / 256, 256>>>(user_emb, item_emb);
    mark_kernel<<<(BATCH + 255) / 256, 256>>>(users);
    hist_kernel<<<(NNZ + 255) / 256, 256>>>(rows);
    scanA_kernel<<<SCAN_BLKS, 1024>>>();
    scanB_kernel<<<1, 256>>>();
    scanC_kernel<<<SCAN_BLKS, 1024>>>();
    scatter_kernel<<<(NNZ + 255) / 256, 256>>>(rows, cols, vals);

    const int layer_blocks = (N_TOTAL + 63) / 64;
    fused_layer_kernel<1><<<layer_blocks, 256>>>(egoA, egoB, Ws[0], bs[0]);
    fused_layer_kernel<1><<<layer_blocks, 256>>>(egoB, egoA, Ws[1], bs[1]);
    fused_layer_kernel<0><<<layer_blocks, 256>>>(egoA, egoB, Ws[2], bs[2]);

    gather_kernel<<<(BATCH * 16 + 255) / 256, 256>>>(users, user_emb, out);
}

// round 6
// speedup vs baseline: 2.9778x; 1.1269x over previous
#include <cuda_runtime.h>
#include <cuda_fp16.h>
#include <math.h>

#define N_USER  50000
#define N_ITEM  100000
#define N_TOTAL 150000
#define NNZ     3000000
#define EMB     64
#define BATCH   4096
#define SCAN_BLKS 147   // ceil(150000/1024)

// ---------------- scratch (no allocation allowed -> device globals) --------
__device__ __half2 g_egoA[(size_t)N_TOTAL * 32];  // 19.2 MB (ego ping, fp16)
__device__ __half2 g_egoB[(size_t)N_TOTAL * 32];  // 19.2 MB (ego pong, fp16)
__device__ float   g_total[(size_t)N_USER * EMB]; // 12.8 MB
__device__ unsigned char g_used[N_USER];
__device__ unsigned char g_act2[N_TOTAL];
__device__ int   g_list2[N_TOTAL];
__device__ int   g_list3[BATCH];
__device__ int   g_n2, g_n3;
__device__ int   g_cnt[N_TOTAL];
__device__ int   g_row_start[N_TOTAL + 1];
__device__ int   g_row_ptr[N_TOTAL];
__device__ int   g_blk[256];
__device__ int2  g_edge[NNZ];                     // 24 MB (col, val-bits)

// ---------------- packed f32x2 helpers -------------------------------------
__device__ __forceinline__ unsigned long long ffma2(unsigned long long a,
                                                    unsigned long long b,
                                                    unsigned long long c) {
    unsigned long long d;
    asm("fma.rn.f32x2 %0, %1, %2, %3;" : "=l"(d) : "l"(a), "l"(b), "l"(c));
    return d;
}
__device__ __forceinline__ unsigned long long pack2(float lo, float hi) {
    unsigned long long d;
    asm("mov.b64 %0, {%1, %2};" : "=l"(d) : "f"(lo), "f"(hi));
    return d;
}
__device__ __forceinline__ void unpack2(unsigned long long v, float& lo, float& hi) {
    asm("mov.b64 {%0, %1}, %2;" : "=f"(lo), "=f"(hi) : "l"(v));
}

// ---------------- init: egoA = fp16(concat); zero everything ---------------
__global__ void init_kernel(const float* __restrict__ ue,
                            const float* __restrict__ ie) {
    const int U4 = N_USER * EMB / 4;
    const int T4 = N_TOTAL * EMB / 4;
    int idx = blockIdx.x * blockDim.x + threadIdx.x;
    if (idx < T4) {
        float4 v = (idx < U4)
            ? reinterpret_cast<const float4*>(ue)[idx]
            : reinterpret_cast<const float4*>(ie)[idx - U4];
        g_egoA[2 * idx]     = __floats2half2_rn(v.x, v.y);
        g_egoA[2 * idx + 1] = __floats2half2_rn(v.z, v.w);
        if (idx < U4)
            reinterpret_cast<float4*>(g_total)[idx] = make_float4(0.f, 0.f, 0.f, 0.f);
    }
    if (idx < N_TOTAL) { g_cnt[idx] = 0; g_act2[idx] = 0; }
    if (idx < N_USER)  g_used[idx] = 0;
    if (idx == 0) { g_n2 = 0; g_n3 = 0; }
}

// ---------------- mark sampled users ---------------------------------------
__global__ void mark_kernel(const int* __restrict__ users) {
    int i = blockIdx.x * blockDim.x + threadIdx.x;
    if (i < BATCH) g_used[__ldg(users + i)] = 1;
}

// ---------------- compact used users -> list3 -------------------------------
__global__ void build_act3_kernel() {
    int i = blockIdx.x * blockDim.x + threadIdx.x;
    if (i < N_USER && g_used[i]) {
        int p = atomicAdd(&g_n3, 1);
        g_list3[p] = i;
    }
}

// ---------------- mark layer-2 active rows (users + their neighbor cols) ----
__global__ void mark_act2_kernel() {
    int gid  = blockIdx.x * blockDim.x + threadIdx.x;
    int wid  = gid >> 5, lane = gid & 31;
    int n3 = g_n3;
    if (wid >= n3) return;
    int u = __ldg(&g_list3[wid]);
    if (lane == 0) g_act2[u] = 1;
    int s = __ldg(&g_row_start[u]);
    int e = __ldg(&g_row_start[u + 1]);
    for (int i = s + lane; i < e; i += 32)
        g_act2[__ldg(&g_edge[i]).x] = 1;
}

// ---------------- compact layer-2 active rows -> list2 ----------------------
__global__ void build_act2_kernel() {
    int i = blockIdx.x * blockDim.x + threadIdx.x;
    if (i < N_TOTAL && g_act2[i]) {
        int p = atomicAdd(&g_n2, 1);
        g_list2[p] = i;
    }
}

// ---------------- CSR build: histogram -------------------------------------
__global__ void hist_kernel(const int* __restrict__ rows) {
    int idx = blockIdx.x * blockDim.x + threadIdx.x;
    if (idx < NNZ) atomicAdd(&g_cnt[__ldg(rows + idx)], 1);
}

// ---------------- hierarchical scan -----------------------------------------
__global__ void __launch_bounds__(1024) scanA_kernel() {
    __shared__ int sh[1024];
    int t = threadIdx.x;
    int i = blockIdx.x * 1024 + t;
    int v = (i < N_TOTAL) ? g_cnt[i] : 0;
    sh[t] = v;
    __syncthreads();
    for (int off = 1; off < 1024; off <<= 1) {
        int x = (t >= off) ? sh[t - off] : 0;
        __syncthreads();
        sh[t] += x;
        __syncthreads();
    }
    if (i < N_TOTAL) g_row_start[i] = sh[t] - v;
    if (t == 1023) g_blk[blockIdx.x] = sh[1023];
}
__global__ void __launch_bounds__(256) scanB_kernel() {
    __shared__ int sh[256];
    int t = threadIdx.x;
    int v = (t < SCAN_BLKS) ? g_blk[t] : 0;
    sh[t] = v;
    __syncthreads();
    for (int off = 1; off < 256; off <<= 1) {
        int x = (t >= off) ? sh[t - off] : 0;
        __syncthreads();
        sh[t] += x;
        __syncthreads();
    }
    if (t < SCAN_BLKS) g_blk[t] = sh[t] - v;
}
__global__ void __launch_bounds__(1024) scanC_kernel() {
    int i = blockIdx.x * 1024 + threadIdx.x;
    if (i < N_TOTAL) {
        int v = g_row_start[i] + g_blk[blockIdx.x];
        g_row_start[i] = v;
        g_row_ptr[i]   = v;
    }
    if (i == 0) g_row_start[N_TOTAL] = NNZ;
}

// ---------------- CSR build: scatter edges ----------------------------------
__global__ void scatter_kernel(const int* __restrict__ rows,
                               const int* __restrict__ cols,
                               const float* __restrict__ vals) {
    int idx = blockIdx.x * blockDim.x + threadIdx.x;
    if (idx < NNZ) {
        int r = __ldg(rows + idx);
        int pos = atomicAdd(&g_row_ptr[r], 1);
        g_edge[pos] = make_int2(__ldg(cols + idx),
                                __float_as_int(__ldg(vals + idx)));
    }
}

// ---------------- fused SpMM + dense layer ----------------------------------
// MODE 0: all rows, write ego.  MODE 1: row list, write ego.
// MODE 2: row list, no ego write (last layer).
template <int MODE>
__global__ void __launch_bounds__(256)
fused_layer_kernel(const __half2* __restrict__ ego_src,
                   __half2* __restrict__ ego_dst,
                   const float* __restrict__ W, const float* __restrict__ b,
                   const int* __restrict__ rowlist, const int* __restrict__ pn) {
    __shared__ float sW[64 * 64];
    __shared__ float sS[64 * 66];
    __shared__ float sInv[64];
    __shared__ int   sList[64];
    __shared__ unsigned char sUse[64];

    int tid  = threadIdx.x;
    int row0 = blockIdx.x * 64;
    int n = (MODE == 0) ? N_TOTAL : __ldg(pn);
    if (row0 >= n) return;
    int warp = tid >> 5, lane = tid & 31;

    for (int i = tid; i < 1024; i += 256)
        reinterpret_cast<float4*>(sW)[i] =
            __ldg(reinterpret_cast<const float4*>(W) + i);
    if (tid < 64) {
        int idx = row0 + tid;
        int grow = (idx < n) ? ((MODE == 0) ? idx : __ldg(rowlist + idx)) : -1;
        sList[tid] = grow;
        sUse[tid] = (grow >= 0 && grow < N_USER) ? g_used[grow] : 0;
    }
    __syncthreads();

    // ---- phase 1: pull-SpMM, warp per row, unroll-4 for MLP ---------------
    for (int rr = warp; rr < 64; rr += 8) {
        int grow = sList[rr];
        float acc0 = 0.f, acc1 = 0.f;
        if (grow >= 0) {
            int s = __ldg(&g_row_start[grow]);
            int e = __ldg(&g_row_start[grow + 1]);
            int i = s;
            for (; i + 4 <= e; i += 4) {
                int2 e0 = __ldg(&g_edge[i]);
                int2 e1 = __ldg(&g_edge[i + 1]);
                int2 e2 = __ldg(&g_edge[i + 2]);
                int2 e3 = __ldg(&g_edge[i + 3]);
                __half2 x0 = __ldg(ego_src + (size_t)e0.x * 32 + lane);
                __half2 x1 = __ldg(ego_src + (size_t)e1.x * 32 + lane);
                __half2 x2 = __ldg(ego_src + (size_t)e2.x * 32 + lane);
                __half2 x3 = __ldg(ego_src + (size_t)e3.x * 32 + lane);
                float2 f0 = __half22float2(x0);
                float2 f1 = __half22float2(x1);
                float2 f2 = __half22float2(x2);
                float2 f3 = __half22float2(x3);
                float v0 = __int_as_float(e0.y), v1 = __int_as_float(e1.y);
                float v2 = __int_as_float(e2.y), v3 = __int_as_float(e3.y);
                acc0 += v0 * f0.x + v1 * f1.x + v2 * f2.x + v3 * f3.x;
                acc1 += v0 * f0.y + v1 * f1.y + v2 * f2.y + v3 * f3.y;
            }
            for (; i < e; i++) {
                int2 e0 = __ldg(&g_edge[i]);
                __half2 x0 = __ldg(ego_src + (size_t)e0.x * 32 + lane);
                float2 f0 = __half22float2(x0);
                float v0 = __int_as_float(e0.y);
                acc0 += v0 * f0.x;
                acc1 += v0 * f0.y;
            }
        }
        sS[rr * 66 + lane * 2]     = acc0;
        sS[rr * 66 + lane * 2 + 1] = acc1;
    }
    __syncthreads();

    // ---- phase 2: 64x64 GEMM, 4x4 per thread, FFMA2 -----------------------
    int tc = tid & 15, tr = tid >> 4;
    int r0 = tr * 4, c0 = tc * 4;
    unsigned long long acc[4][2];
    {
        float4 bb = __ldg(reinterpret_cast<const float4*>(b) + tc);
        unsigned long long b01 = pack2(bb.x, bb.y);
        unsigned long long b23 = pack2(bb.z, bb.w);
#pragma unroll
        for (int r = 0; r < 4; r++) { acc[r][0] = b01; acc[r][1] = b23; }
    }
#pragma unroll 4
    for (int k = 0; k < 64; k++) {
        float4 w = *reinterpret_cast<const float4*>(sW + k * 64 + c0);
        unsigned long long w01 = pack2(w.x, w.y);
        unsigned long long w23 = pack2(w.z, w.w);
#pragma unroll
        for (int r = 0; r < 4; r++) {
            float s = sS[(r0 + r) * 66 + k];
            unsigned long long sd = pack2(s, s);
            acc[r][0] = ffma2(sd, w01, acc[r][0]);
            acc[r][1] = ffma2(sd, w23, acc[r][1]);
        }
    }

    float h[4][4];
    float sq[4];
#pragma unroll
    for (int r = 0; r < 4; r++) {
        float x0, x1, x2, x3;
        unpack2(acc[r][0], x0, x1);
        unpack2(acc[r][1], x2, x3);
        x0 = (x0 >= 0.f) ? x0 : 0.2f * x0;
        x1 = (x1 >= 0.f) ? x1 : 0.2f * x1;
        x2 = (x2 >= 0.f) ? x2 : 0.2f * x2;
        x3 = (x3 >= 0.f) ? x3 : 0.2f * x3;
        h[r][0] = x0; h[r][1] = x1; h[r][2] = x2; h[r][3] = x3;
        sq[r] = x0 * x0 + x1 * x1 + x2 * x2 + x3 * x3;
    }
#pragma unroll
    for (int off = 8; off > 0; off >>= 1) {
#pragma unroll
        for (int r = 0; r < 4; r++)
            sq[r] += __shfl_down_sync(0xffffffffu, sq[r], off, 16);
    }

    __syncthreads();
    if (tc == 0) {
#pragma unroll
        for (int r = 0; r < 4; r++)
            sInv[r0 + r] = 1.0f / fmaxf(sqrtf(sq[r]), 1e-12f);
    }
#pragma unroll
    for (int r = 0; r < 4; r++) {
        float* p = sS + (r0 + r) * 66 + c0;
        p[0] = h[r][0]; p[1] = h[r][1]; p[2] = h[r][2]; p[3] = h[r][3];
    }
    __syncthreads();

    // writeback ego (fp16)
    if (MODE != 2) {
        for (int i = tid; i < 2048; i += 256) {
            int r = i >> 5, c2 = i & 31;
            int grow = sList[r];
            if (grow >= 0) {
                float lo = sS[r * 66 + c2 * 2];
                float hi = sS[r * 66 + c2 * 2 + 1];
                ego_dst[(size_t)grow * 32 + c2] = __floats2half2_rn(lo, hi);
            }
        }
    }
    // writeback total (only sampled user rows)
    for (int i = tid; i < 4096; i += 256) {
        int r = i >> 6, c = i & 63;
        if (sUse[r]) {
            int grow = sList[r];
            g_total[(size_t)grow * 64 + c] += sS[r * 66 + c] * sInv[r];
        }
    }
}

// ---------------- final gather: out = user_emb[users] + total[users] -------
__global__ void gather_kernel(const int* __restrict__ users,
                              const float* __restrict__ ue,
                              float* __restrict__ out) {
    int idx = blockIdx.x * blockDim.x + threadIdx.x;
    if (idx < BATCH * 16) {
        int i = idx >> 4, j = idx & 15;
        int u = __ldg(users + i);
        float4 a = reinterpret_cast<const float4*>(ue)[(size_t)u * 16 + j];
        float4 t = reinterpret_cast<const float4*>(g_total)[(size_t)u * 16 + j];
        reinterpret_cast<float4*>(out)[(size_t)i * 16 + j] =
            make_float4(a.x + t.x, a.y + t.y, a.z + t.z, a.w + t.w);
    }
}

// ---------------------------------------------------------------------------
extern "C" void kernel_launch(void* const* d_in, const int* in_sizes, int n_in,
                              void* d_out, int out_size) {
    const int*   users    = (const int*)  d_in[0];
    const int*   rows     = (const int*)  d_in[1];
    const int*   cols     = (const int*)  d_in[2];
    const float* vals     = (const float*)d_in[3];
    const float* user_emb = (const float*)d_in[4];
    const float* item_emb = (const float*)d_in[5];
    const float* Ws[3] = {(const float*)d_in[6], (const float*)d_in[8],  (const float*)d_in[10]};
    const float* bs[3] = {(const float*)d_in[7], (const float*)d_in[9],  (const float*)d_in[11]};
    float* out = (float*)d_out;

    __half2* egoA; cudaGetSymbolAddress((void**)&egoA, g_egoA);
    __half2* egoB; cudaGetSymbolAddress((void**)&egoB, g_egoB);
    int* list2;   cudaGetSymbolAddress((void**)&list2, g_list2);
    int* list3;   cudaGetSymbolAddress((void**)&list3, g_list3);
    int* pn2;     cudaGetSymbolAddress((void**)&pn2, g_n2);
    int* pn3;     cudaGetSymbolAddress((void**)&pn3, g_n3);

    const int T4 = N_TOTAL * EMB / 4;
    init_kernel<<<(T4 + 255) / 256, 256>>>(user_emb, item_emb);
    mark_kernel<<<(BATCH + 255) / 256, 256>>>(users);
    build_act3_kernel<<<(N_USER + 255) / 256, 256>>>();
    hist_kernel<<<(NNZ + 255) / 256, 256>>>(rows);
    scanA_kernel<<<SCAN_BLKS, 1024>>>();
    scanB_kernel<<<1, 256>>>();
    scanC_kernel<<<SCAN_BLKS, 1024>>>();
    scatter_kernel<<<(NNZ + 255) / 256, 256>>>(rows, cols, vals);
    mark_act2_kernel<<<(BATCH * 32 + 255) / 256, 256>>>();
    build_act2_kernel<<<(N_TOTAL + 255) / 256, 256>>>();

    const int full_blocks = (N_TOTAL + 63) / 64;
    fused_layer_kernel<0><<<full_blocks, 256>>>(egoA, egoB, Ws[0], bs[0], nullptr, nullptr);
    fused_layer_kernel<1><<<full_blocks, 256>>>(egoB, egoA, Ws[1], bs[1], list2, pn2);
    fused_layer_kernel<2><<<(BATCH + 63) / 64, 256>>>(egoA, nullptr, Ws[2], bs[2], list3, pn3);

    gather_kernel<<<(BATCH * 16 + 255) / 256, 256>>>(users, user_emb, out);
}